// round 16
// baseline (speedup 1.0000x reference)
#include <cuda_runtime.h>

static constexpr int H = 512;
static constexpr int W = 512;
static constexpr unsigned FULL = 0xFFFFFFFFu;

__device__ __forceinline__ float med3f(float a, float b, float c) {
    return fmaxf(fminf(a, b), fminf(fmaxf(a, b), c));
}

// Streamed row: merge row t into pre-sorted pair (p,q) column-by-column while
// doing the horizontal merge over a sliding 4-column triple window.
// Identical op count to the array version; ~1/3 the live triple state.
__device__ __forceinline__ void row_stream(const float* t, const float* p, const float* q,
                                            float et, float ep, float eq,
                                            bool isL, bool isR,
                                            float* __restrict__ orow, int c0) {
    // Triple for local col j+1 (t/p/q index j).
    auto trip = [&](int j, float& lo, float& md, float& hi) {
        float m = fmaxf(t[j], p[j]);
        lo = fminf(t[j], p[j]);
        hi = fmaxf(m, q[j]);
        md = fminf(m, q[j]);
    };

    // Cols 1 and 8 first — they feed the neighbor shuffles.
    float l1, m1, h1, l8, m8, h8;
    trip(0, l1, m1, h1);
    trip(7, l8, m8, h8);

    // Edge triple (meaningful in lanes 0/31 only).
    float em = fmaxf(et, ep);
    float elo = fminf(et, ep), ehi = fmaxf(em, eq), emd = fminf(em, eq);
    float Ll = __shfl_up_sync(FULL, l8, 1);
    float Lm = __shfl_up_sync(FULL, m8, 1);
    float Lh = __shfl_up_sync(FULL, h8, 1);
    float Rl = __shfl_down_sync(FULL, l1, 1);
    float Rm = __shfl_down_sync(FULL, m1, 1);
    float Rh = __shfl_down_sync(FULL, h1, 1);
    if (isL) { Ll = elo; Lm = emd; Lh = ehi; }
    if (isR) { Rl = elo; Rm = emd; Rh = ehi; }

    // Sliding window: a = col 2k, b = col 2k+1.
    float al = Ll, am = Lm, ah = Lh;
    float bl = l1, bm = m1, bh = h1;
    float o[8];
#pragma unroll
    for (int k = 0; k < 4; k++) {
        float cl, cm, ch, dl, dm, dh;          // cols 2k+2, 2k+3
        if (k < 3) {
            trip(2 * k + 1, cl, cm, ch);
            trip(2 * k + 2, dl, dm, dh);
        } else {
            cl = l8; cm = m8; ch = h8;          // col 8 (precomputed)
            dl = Rl; dm = Rm; dh = Rh;          // col 9 = R edge
        }
        // Shared middle pair (b,c) serves windows 2k and 2k+1.
        float pxl = fmaxf(bl, cl), pzl = fminf(bh, ch);
        float mn = fminf(bm, cm), mx = fmaxf(bm, cm);
        float X0 = fmaxf(al, pxl), Z0 = fminf(ah, pzl), Y0 = fmaxf(mn, fminf(mx, am));
        float X1 = fmaxf(pxl, dl), Z1 = fminf(pzl, dh), Y1 = fmaxf(mn, fminf(mx, dm));
        o[2 * k]     = med3f(X0, Y0, Z0);
        o[2 * k + 1] = med3f(X1, Y1, Z1);
        al = cl; am = cm; ah = ch;              // rotate (renaming when unrolled)
        bl = dl; bm = dm; bh = dh;
    }
    *(float4*)(orow + c0)     = make_float4(o[0], o[1], o[2], o[3]);
    *(float4*)(orow + c0 + 4) = make_float4(o[4], o[5], o[6], o[7]);
}

__global__ __launch_bounds__(128, 7)
void median3x3_kernel(const float* __restrict__ in, float* __restrict__ out, int nimg) {
    const int gwarp = (blockIdx.x * blockDim.x + threadIdx.x) >> 5;
    const int lane = threadIdx.x & 31;

    // Per image: 128 row-quads (4 output rows each) x 2 warp-column-groups (256 cols each).
    const int img = gwarp >> 8;
    if (img >= nimg) return;
    const int rem = gwarp & 255;
    const int y0 = (rem >> 1) << 2;                  // 0,4,...,508
    const int c0 = ((rem & 1) << 8) + (lane << 3);   // 8 columns per lane

    const float* __restrict__ base = in + (size_t)img * (H * W);
    float* __restrict__ obase = out + (size_t)img * (H * W);

    const bool topOK = (y0 > 0);
    const bool botOK = (y0 + 4 < H);
    const bool isL = (lane == 0);
    const bool isR = (lane == 31);
    const int ecol = isL ? (c0 - 1) : (c0 + 8);
    const bool ev = (isL | isR) && ((unsigned)ecol < (unsigned)W);
    const float4 z4 = make_float4(0.f, 0.f, 0.f, 0.f);

    // ---- Phase: rows i1,i2 -> shared pair A (r1 dies immediately) ----
    float p[8], q[8], r2[8];
    float e1, e2;
    {
        float4 v1a = *(const float4*)(base + (y0    ) * W + c0);
        float4 v1b = *(const float4*)(base + (y0    ) * W + c0 + 4);
        float4 v2a = *(const float4*)(base + (y0 + 1) * W + c0);
        float4 v2b = *(const float4*)(base + (y0 + 1) * W + c0 + 4);
        e1 = ev ? base[(y0    ) * W + ecol] : 0.f;
        e2 = ev ? base[(y0 + 1) * W + ecol] : 0.f;
        r2[0] = v2a.x; r2[1] = v2a.y; r2[2] = v2a.z; r2[3] = v2a.w;
        r2[4] = v2b.x; r2[5] = v2b.y; r2[6] = v2b.z; r2[7] = v2b.w;
        float r1[8] = {v1a.x, v1a.y, v1a.z, v1a.w, v1b.x, v1b.y, v1b.z, v1b.w};
#pragma unroll
        for (int i = 0; i < 8; i++) {
            p[i] = fminf(r1[i], r2[i]);
            q[i] = fmaxf(r1[i], r2[i]);
        }
    }
    const float epA = fminf(e1, e2), eqA = fmaxf(e1, e2);

    // ---- Row o0 = (i0, i1, i2): load i0 just-in-time, dies inside ----
    {
        float4 v0a = topOK ? *(const float4*)(base + (y0 - 1) * W + c0)     : z4;
        float4 v0b = topOK ? *(const float4*)(base + (y0 - 1) * W + c0 + 4) : z4;
        float e0 = (ev && topOK) ? base[(y0 - 1) * W + ecol] : 0.f;
        float t0[8] = {v0a.x, v0a.y, v0a.z, v0a.w, v0b.x, v0b.y, v0b.z, v0b.w};
        row_stream(t0, p, q, e0, epA, eqA, isL, isR, obase + (y0    ) * W, c0);
    }

    // ---- Row o1 = (i1, i2, i3): r3 persists (needed for pair B) ----
    float r3[8];
    float e3;
    {
        float4 v3a = *(const float4*)(base + (y0 + 2) * W + c0);
        float4 v3b = *(const float4*)(base + (y0 + 2) * W + c0 + 4);
        e3 = ev ? base[(y0 + 2) * W + ecol] : 0.f;
        r3[0] = v3a.x; r3[1] = v3a.y; r3[2] = v3a.z; r3[3] = v3a.w;
        r3[4] = v3b.x; r3[5] = v3b.y; r3[6] = v3b.z; r3[7] = v3b.w;
        row_stream(r3, p, q, e3, epA, eqA, isL, isR, obase + (y0 + 1) * W, c0);
    }

    // ---- Pair B = sort(i3, i4): r4 dies immediately; pair A storage reused ----
    float e4;
    {
        float4 v4a = *(const float4*)(base + (y0 + 3) * W + c0);
        float4 v4b = *(const float4*)(base + (y0 + 3) * W + c0 + 4);
        e4 = ev ? base[(y0 + 3) * W + ecol] : 0.f;
        float r4[8] = {v4a.x, v4a.y, v4a.z, v4a.w, v4b.x, v4b.y, v4b.z, v4b.w};
#pragma unroll
        for (int i = 0; i < 8; i++) {
            float mn = fminf(r3[i], r4[i]);
            float mx = fmaxf(r3[i], r4[i]);
            p[i] = mn;
            q[i] = mx;
        }
    }
    const float epB = fminf(e3, e4), eqB = fmaxf(e3, e4);

    // ---- Row o2 = (i2, i3, i4): t = r2 (dies here) ----
    row_stream(r2, p, q, e2, epB, eqB, isL, isR, obase + (y0 + 2) * W, c0);

    // ---- Row o3 = (i3, i4, i5): load i5 just-in-time ----
    {
        float4 v5a = botOK ? *(const float4*)(base + (y0 + 4) * W + c0)     : z4;
        float4 v5b = botOK ? *(const float4*)(base + (y0 + 4) * W + c0 + 4) : z4;
        float e5 = (ev && botOK) ? base[(y0 + 4) * W + ecol] : 0.f;
        float t5[8] = {v5a.x, v5a.y, v5a.z, v5a.w, v5b.x, v5b.y, v5b.z, v5b.w};
        row_stream(t5, p, q, e5, epB, eqB, isL, isR, obase + (y0 + 3) * W, c0);
    }
}

extern "C" void kernel_launch(void* const* d_in, const int* in_sizes, int n_in,
                              void* d_out, int out_size) {
    const float* x = (const float*)d_in[0];
    float* y = (float*)d_out;
    const int nimg = in_sizes[0] / (H * W);                  // B*C images
    const int warps = nimg * (H / 4) * (W / 256);            // 128 row-quads x 2 groups
    const int threads = warps * 32;
    const int block = 128;
    const int grid = (threads + block - 1) / block;
    median3x3_kernel<<<grid, block>>>(x, y, nimg);
}